// round 3
// baseline (speedup 1.0000x reference)
#include <cuda_runtime.h>
#include <cuda_bf16.h>

// ---------------------------------------------------------------------------
// Swin WindowAttention, fp32 baseline (double-buffered SGEMM).
//   x:(2048,49,512) -> qkv GEMM -> per-(b,h) attention (49x49, d=32) -> proj GEMM
// Stage layout:
//   g_q/g_k/g_v : (B, H, N, d)   q pre-scaled by 1/sqrt(d)
//   g_ao        : (B, N, C)      attention output (proj GEMM input)
// ---------------------------------------------------------------------------

#define DIM   512
#define NHEAD 16
#define HD    32
#define NTOK  49
#define NBAT  2048
#define MROWS (NBAT * NTOK)          // 100352
#define KDIM  512
#define NWIN  64
#define SCALE 0.17677669529663687f   // 32^-0.5

__device__ float g_q[(size_t)NBAT * NHEAD * NTOK * HD];
__device__ float g_k[(size_t)NBAT * NHEAD * NTOK * HD];
__device__ float g_v[(size_t)NBAT * NHEAD * NTOK * HD];
__device__ float g_ao[(size_t)NBAT * NTOK * DIM];

// ---------------------------------------------------------------------------
// Tiled SGEMM: C[m,o] = sum_k A[m,k] * B[o,k]  (+ bias[o])
// MODE 0: A = x, B = qkv_w, scatter into g_q/g_k/g_v (q scaled).
// MODE 1: A = g_ao, B = proj_w, write C = d_out with bias.
// BM=BN=128, BK=8, TM=TN=8, 256 threads, double-buffered smem.
// One __syncthreads per K-step: compute reads buf c while the next tile's
// global loads land in buf c^1 (ordered by the PREVIOUS iteration's barrier).
// ---------------------------------------------------------------------------
template <int MODE>
__global__ __launch_bounds__(256) void sgemm_kernel(
    const float* __restrict__ A, const float* __restrict__ Bm,
    const float* __restrict__ bias, float* __restrict__ C)
{
    constexpr int BM = 128, BN = 128, BK = 8, TM = 8, TN = 8;
    __shared__ float As[2][BK][BM];
    __shared__ float Bs[2][BK][BN];

    const int tid  = threadIdx.x;
    const int crow = blockIdx.y * BM;
    const int ccol = blockIdx.x * BN;

    const float* Abase = (MODE == 0) ? A : g_ao;

    const int ldRow = tid >> 1;          // 0..127
    const int ldCol = (tid & 1) * 4;     // 0 or 4
    const int tRow  = (tid >> 4) * TM;   // 0..120
    const int tCol  = (tid & 15) * TN;   // 0..120

    float acc[TM][TN];
#pragma unroll
    for (int i = 0; i < TM; i++)
#pragma unroll
        for (int j = 0; j < TN; j++) acc[i][j] = 0.f;

    const float* Ap = Abase + (size_t)(crow + ldRow) * KDIM + ldCol;
    const float* Bp = Bm    + (size_t)(ccol + ldRow) * KDIM + ldCol;

    // prologue: tile 0 -> buffer 0
    {
        float4 a4 = *(const float4*)(Ap);
        As[0][ldCol + 0][ldRow] = a4.x;
        As[0][ldCol + 1][ldRow] = a4.y;
        As[0][ldCol + 2][ldRow] = a4.z;
        As[0][ldCol + 3][ldRow] = a4.w;
        float4 b4 = *(const float4*)(Bp);
        Bs[0][ldCol + 0][ldRow] = b4.x;
        Bs[0][ldCol + 1][ldRow] = b4.y;
        Bs[0][ldCol + 2][ldRow] = b4.z;
        Bs[0][ldCol + 3][ldRow] = b4.w;
    }
    __syncthreads();

    int cur = 0;
    for (int k0 = 0; k0 < KDIM; k0 += BK) {
        const int nk = k0 + BK;
        float4 na, nb;
        if (nk < KDIM) {                  // issue next tile's loads early
            na = *(const float4*)(Ap + nk);
            nb = *(const float4*)(Bp + nk);
        }

#pragma unroll
        for (int kk = 0; kk < BK; kk++) {
            float4 m0 = *(const float4*)&As[cur][kk][tRow];
            float4 m1 = *(const float4*)&As[cur][kk][tRow + 4];
            float4 n0 = *(const float4*)&Bs[cur][kk][tCol];
            float4 n1 = *(const float4*)&Bs[cur][kk][tCol + 4];
            float rm[TM] = {m0.x, m0.y, m0.z, m0.w, m1.x, m1.y, m1.z, m1.w};
            float rn[TN] = {n0.x, n0.y, n0.z, n0.w, n1.x, n1.y, n1.z, n1.w};
#pragma unroll
            for (int i = 0; i < TM; i++)
#pragma unroll
                for (int j = 0; j < TN; j++)
                    acc[i][j] += rm[i] * rn[j];
        }

        if (nk < KDIM) {
            const int nxt = cur ^ 1;
            As[nxt][ldCol + 0][ldRow] = na.x;
            As[nxt][ldCol + 1][ldRow] = na.y;
            As[nxt][ldCol + 2][ldRow] = na.z;
            As[nxt][ldCol + 3][ldRow] = na.w;
            Bs[nxt][ldCol + 0][ldRow] = nb.x;
            Bs[nxt][ldCol + 1][ldRow] = nb.y;
            Bs[nxt][ldCol + 2][ldRow] = nb.z;
            Bs[nxt][ldCol + 3][ldRow] = nb.w;
            __syncthreads();
            cur = nxt;
        }
    }

    if (MODE == 0) {
#pragma unroll
        for (int i = 0; i < TM; i++) {
            const int m  = crow + tRow + i;
            const int bi = m / NTOK;
            const int ni = m - bi * NTOK;
#pragma unroll
            for (int j = 0; j < TN; j++) {
                const int o = ccol + tCol + j;
                float v = acc[i][j] + bias[o];
                const int three = o >> 9;       // 0:q 1:k 2:v
                const int rem   = o & 511;
                const int hh    = rem >> 5;
                const int dd    = rem & 31;
                const size_t dst = (((size_t)bi * NHEAD + hh) * NTOK + ni) * HD + dd;
                if (three == 0)      g_q[dst] = v * SCALE;
                else if (three == 1) g_k[dst] = v;
                else                 g_v[dst] = v;
            }
        }
    } else {
#pragma unroll
        for (int i = 0; i < TM; i++) {
            const int m = crow + tRow + i;
            float* cp = C + (size_t)m * DIM + ccol + tCol;
#pragma unroll
            for (int j4 = 0; j4 < TN; j4 += 4) {
                float4 w;
                w.x = acc[i][j4 + 0] + bias[ccol + tCol + j4 + 0];
                w.y = acc[i][j4 + 1] + bias[ccol + tCol + j4 + 1];
                w.z = acc[i][j4 + 2] + bias[ccol + tCol + j4 + 2];
                w.w = acc[i][j4 + 3] + bias[ccol + tCol + j4 + 3];
                *(float4*)(cp + j4) = w;
            }
        }
    }
}

// ---------------------------------------------------------------------------
// Attention: one block per (b, h). 256 threads.
//   s = q@k^T + rel_pos_bias(h) + mask[b % 64]; softmax rows; out = s@v
//   writes g_ao[b][n][h*32+d]
// ---------------------------------------------------------------------------
__global__ __launch_bounds__(256) void attn_kernel(
    const float* __restrict__ mask, const float* __restrict__ rpb)
{
    const int bh = blockIdx.x;
    const int b  = bh >> 4;
    const int h  = bh & 15;

    __shared__ float sq[NTOK][HD + 1];
    __shared__ float sk[NTOK][HD + 1];
    __shared__ float sv[NTOK][HD + 1];
    __shared__ float s[NTOK][52];
    __shared__ float sb[169];

    const int tid = threadIdx.x;
    const size_t base = (size_t)bh * NTOK * HD;
    const float* qb = g_q + base;
    const float* kb = g_k + base;
    const float* vb = g_v + base;

    // load q/k/v (49*32 = 1568 floats each) via float4
    for (int p = tid; p < (NTOK * HD) / 4; p += 256) {
        const int r = p * 4;
        const int i = r >> 5;
        const int c = r & 31;
        float4 t;
        t = *(const float4*)(qb + r);
        sq[i][c] = t.x; sq[i][c + 1] = t.y; sq[i][c + 2] = t.z; sq[i][c + 3] = t.w;
        t = *(const float4*)(kb + r);
        sk[i][c] = t.x; sk[i][c + 1] = t.y; sk[i][c + 2] = t.z; sk[i][c + 3] = t.w;
        t = *(const float4*)(vb + r);
        sv[i][c] = t.x; sv[i][c + 1] = t.y; sv[i][c + 2] = t.z; sv[i][c + 3] = t.w;
    }
    // per-head bias table slice
    for (int p = tid; p < 169; p += 256) sb[p] = rpb[p * NHEAD + h];
    __syncthreads();

    const float* mk = mask + (size_t)(b & (NWIN - 1)) * NTOK * NTOK;

    // scores
    for (int p = tid; p < NTOK * NTOK; p += 256) {
        const int i = p / NTOK;
        const int j = p - i * NTOK;
        float a = 0.f;
#pragma unroll
        for (int kk = 0; kk < HD; kk++) a += sq[i][kk] * sk[j][kk];
        const int yi = i / 7, xi = i - yi * 7;
        const int yj = j / 7, xj = j - yj * 7;
        const int ridx = (yi - yj + 6) * 13 + (xi - xj + 6);
        s[i][j] = a + sb[ridx] + mk[p];
    }
    __syncthreads();

    // softmax: one warp per row
    const int warp = tid >> 5;
    const int lane = tid & 31;
    for (int i = warp; i < NTOK; i += 8) {
        float v1 = (lane < NTOK) ? s[i][lane] : -1e30f;
        float v2 = (lane + 32 < NTOK) ? s[i][lane + 32] : -1e30f;
        float mx = fmaxf(v1, v2);
#pragma unroll
        for (int off = 16; off > 0; off >>= 1)
            mx = fmaxf(mx, __shfl_xor_sync(0xffffffffu, mx, off));
        float e1 = (lane < NTOK) ? __expf(v1 - mx) : 0.f;
        float e2 = (lane + 32 < NTOK) ? __expf(v2 - mx) : 0.f;
        float sm = e1 + e2;
#pragma unroll
        for (int off = 16; off > 0; off >>= 1)
            sm += __shfl_xor_sync(0xffffffffu, sm, off);
        const float inv = 1.f / sm;
        if (lane < NTOK) s[i][lane] = e1 * inv;
        if (lane + 32 < NTOK) s[i][lane + 32] = e2 * inv;
    }
    __syncthreads();

    // out = s @ v  -> g_ao[b][i][h*32+dd]
    for (int p = tid; p < NTOK * HD; p += 256) {
        const int i  = p >> 5;
        const int dd = p & 31;
        float a = 0.f;
#pragma unroll
        for (int j = 0; j < NTOK; j++) a += s[i][j] * sv[j][dd];
        g_ao[((size_t)b * NTOK + i) * DIM + h * HD + dd] = a;
    }
}

extern "C" void kernel_launch(void* const* d_in, const int* in_sizes, int n_in,
                              void* d_out, int out_size)
{
    const float* x      = (const float*)d_in[0];
    const float* mask   = (const float*)d_in[1];
    const float* qkv_w  = (const float*)d_in[2];
    const float* qkv_b  = (const float*)d_in[3];
    const float* proj_w = (const float*)d_in[4];
    const float* proj_b = (const float*)d_in[5];
    const float* rpb    = (const float*)d_in[6];
    float* out = (float*)d_out;

    // GEMM1: (100352 x 512) @ (512 x 1536)
    sgemm_kernel<0><<<dim3(1536 / 128, MROWS / 128), 256>>>(x, qkv_w, qkv_b, nullptr);
    // attention: one block per (b, h)
    attn_kernel<<<NBAT * NHEAD, 256>>>(mask, rpb);
    // GEMM2: (100352 x 512) @ (512 x 512)
    sgemm_kernel<1><<<dim3(DIM / 128, MROWS / 128), 256>>>(nullptr, proj_w, proj_b, out);
}

// round 9
// speedup vs baseline: 1.9967x; 1.9967x over previous
#include <cuda_runtime.h>
#include <cuda_bf16.h>
#include <cstdint>

// ---------------------------------------------------------------------------
// Swin WindowAttention on GB300 (compute_103 PTX target => NO tcgen05).
//   GEMM1/GEMM2: mma.sync.m16n8k16 bf16, 3-term split precision (hi+lo),
//                fp32 accumulate. Attention: fp32 SIMT per-(b,h) block.
// ---------------------------------------------------------------------------

#define DIM   512
#define NHEAD 16
#define HD    32
#define NTOK  49
#define NBAT  2048
#define MROWS (NBAT * NTOK)          // 100352 = 784 * 128
#define KDIM  512
#define NWIN  64
#define SCALE 0.17677669529663687f   // 32^-0.5

__device__ float g_q[(size_t)NBAT * NHEAD * NTOK * HD];
__device__ float g_k[(size_t)NBAT * NHEAD * NTOK * HD];
__device__ float g_v[(size_t)NBAT * NHEAD * NTOK * HD];
__device__ float g_ao[(size_t)NBAT * NTOK * DIM];

__device__ __forceinline__ uint32_t smem_u32(const void* p) {
    uint32_t a;
    asm("{ .reg .u64 t; cvta.to.shared.u64 t, %1; cvt.u32.u64 %0, t; }"
        : "=r"(a) : "l"(p));
    return a;
}

#define LDSM4(r, addr) \
    asm volatile("ldmatrix.sync.aligned.m8n8.x4.shared.b16 {%0,%1,%2,%3}, [%4];" \
                 : "=r"((r)[0]), "=r"((r)[1]), "=r"((r)[2]), "=r"((r)[3]) \
                 : "r"(addr))

#define MMA_BF16(d, a, b0, b1) \
    asm volatile("mma.sync.aligned.m16n8k16.row.col.f32.bf16.bf16.f32 " \
                 "{%0,%1,%2,%3}, {%4,%5,%6,%7}, {%8,%9}, {%0,%1,%2,%3};" \
                 : "+f"((d)[0]), "+f"((d)[1]), "+f"((d)[2]), "+f"((d)[3]) \
                 : "r"((a)[0]), "r"((a)[1]), "r"((a)[2]), "r"((a)[3]), \
                   "r"(b0), "r"(b1))

// ---------------------------------------------------------------------------
// GEMM layout constants: BM=BN=128, BK=32 (fp32), smem rows padded to 80B.
// Per buffer: Ah, Al, Bh, Bl tiles of 128 rows x 32 bf16 (64B data + 16B pad).
// ---------------------------------------------------------------------------
#define ROWB      80
#define TILEB     (128 * ROWB)             // 10240
#define OFF_AH    0
#define OFF_AL    TILEB
#define OFF_BH    (2 * TILEB)
#define OFF_BL    (3 * TILEB)
#define BUFB      (4 * TILEB)              // 40960
#define SMEM_HDR  1024
#define SMEM_TOTAL (SMEM_HDR + 2 * BUFB)   // 82944

// split one float4 into hi/lo bf16x4 (uint2 each)
__device__ __forceinline__ void cvt_split(float4 v, uint2& h, uint2& l) {
    __nv_bfloat162 h01 = __floats2bfloat162_rn(v.x, v.y);
    __nv_bfloat162 h23 = __floats2bfloat162_rn(v.z, v.w);
    float lx = v.x - __bfloat162float(h01.x);
    float ly = v.y - __bfloat162float(h01.y);
    float lz = v.z - __bfloat162float(h23.x);
    float lw = v.w - __bfloat162float(h23.y);
    __nv_bfloat162 l01 = __floats2bfloat162_rn(lx, ly);
    __nv_bfloat162 l23 = __floats2bfloat162_rn(lz, lw);
    h = make_uint2(*(uint32_t*)&h01, *(uint32_t*)&h23);
    l = make_uint2(*(uint32_t*)&l01, *(uint32_t*)&l23);
}

__device__ __forceinline__ void store_split(const float4* pf, char* bufc,
                                            int rb, int k4) {
#pragma unroll
    for (int i = 0; i < 4; i++) {
        uint2 h, l;
        const int so = (rb + 32 * i) * ROWB + k4 * 8;
        cvt_split(pf[i], h, l);
        *(uint2*)(bufc + OFF_AH + so) = h;
        *(uint2*)(bufc + OFF_AL + so) = l;
        cvt_split(pf[4 + i], h, l);
        *(uint2*)(bufc + OFF_BH + so) = h;
        *(uint2*)(bufc + OFF_BL + so) = l;
    }
}

// ---------------------------------------------------------------------------
// D[m,o] = sum_k A[m,k]*B[o,k] + bias[o];  D ≈ Ah*Bh + Ah*Bl + Al*Bh.
// 256 threads, 8 warps: warp grid 4(m) x 2(n), warp tile 32x64.
// MODE 0: A=x, scatter q/k/v (q scaled). MODE 1: A=g_ao, write C.
// ---------------------------------------------------------------------------
template <int MODE>
__global__ __launch_bounds__(256) void mma_gemm(
    const float* __restrict__ Afp, const float* __restrict__ Bfp,
    const float* __restrict__ bias, float* __restrict__ C)
{
    extern __shared__ char smem[];
    float* sBias = (float*)smem;

    const int tid  = threadIdx.x;
    const int wid  = tid >> 5;
    const int lane = tid & 31;
    const int wm   = wid & 3;          // m group: rows wm*32
    const int wn   = wid >> 2;         // n group: cols wn*64
    const int m0 = blockIdx.y * 128;
    const int n0 = blockIdx.x * 128;

    if (tid < 128) sBias[tid] = bias[n0 + tid];

    const float* Asrc = (MODE == 0) ? Afp : g_ao;

    // ldmatrix lane byte-offsets (within a tile)
    const int aoff = (wm * 32 + (lane & 15)) * ROWB + (lane >> 4) * 16;
    int boff[4];
#pragma unroll
    for (int g = 0; g < 4; g++)
        boff[g] = (wn * 64 + g * 16 + ((lane >> 4) << 3) + (lane & 7)) * ROWB +
                  ((lane >> 3) & 1) * 16;

    const uint32_t sbuf = smem_u32(smem) + SMEM_HDR;

    float acc[2][8][4];
#pragma unroll
    for (int mt = 0; mt < 2; mt++)
#pragma unroll
        for (int nt = 0; nt < 8; nt++)
#pragma unroll
            for (int e = 0; e < 4; e++) acc[mt][nt][e] = 0.f;

    const int rb = tid >> 3;          // row base 0..31
    const int k4 = tid & 7;           // float4 slot within 32-k

    float4 pf[8];
#pragma unroll
    for (int i = 0; i < 4; i++) {
        pf[i]     = *(const float4*)(Asrc + (size_t)(m0 + rb + 32 * i) * KDIM + k4 * 4);
        pf[4 + i] = *(const float4*)(Bfp  + (size_t)(n0 + rb + 32 * i) * KDIM + k4 * 4);
    }
    store_split(pf, smem + SMEM_HDR, rb, k4);
    __syncthreads();

    for (int kt = 0; kt < 16; kt++) {
        const int cur = kt & 1;
        if (kt < 15) {
            const int k = (kt + 1) * 32;
#pragma unroll
            for (int i = 0; i < 4; i++) {
                pf[i]     = *(const float4*)(Asrc + (size_t)(m0 + rb + 32 * i) * KDIM + k + k4 * 4);
                pf[4 + i] = *(const float4*)(Bfp  + (size_t)(n0 + rb + 32 * i) * KDIM + k + k4 * 4);
            }
        }

        const uint32_t base = sbuf + cur * BUFB;
#pragma unroll
        for (int kc = 0; kc < 2; kc++) {
            const uint32_t kb = kc * 32;      // 16 bf16 = 32B per k-chunk
            uint32_t ah[2][4], al[2][4], bb[4][4];
#pragma unroll
            for (int mt = 0; mt < 2; mt++) {
                LDSM4(ah[mt], base + OFF_AH + mt * (16 * ROWB) + aoff + kb);
                LDSM4(al[mt], base + OFF_AL + mt * (16 * ROWB) + aoff + kb);
            }
#pragma unroll
            for (int g = 0; g < 4; g++)
                LDSM4(bb[g], base + OFF_BH + boff[g] + kb);
            // Ah*Bh and Al*Bh
#pragma unroll
            for (int mt = 0; mt < 2; mt++)
#pragma unroll
                for (int g = 0; g < 4; g++) {
                    MMA_BF16(acc[mt][2 * g],     ah[mt], bb[g][0], bb[g][1]);
                    MMA_BF16(acc[mt][2 * g + 1], ah[mt], bb[g][2], bb[g][3]);
                    MMA_BF16(acc[mt][2 * g],     al[mt], bb[g][0], bb[g][1]);
                    MMA_BF16(acc[mt][2 * g + 1], al[mt], bb[g][2], bb[g][3]);
                }
            // Ah*Bl
#pragma unroll
            for (int g = 0; g < 4; g++)
                LDSM4(bb[g], base + OFF_BL + boff[g] + kb);
#pragma unroll
            for (int mt = 0; mt < 2; mt++)
#pragma unroll
                for (int g = 0; g < 4; g++) {
                    MMA_BF16(acc[mt][2 * g],     ah[mt], bb[g][0], bb[g][1]);
                    MMA_BF16(acc[mt][2 * g + 1], ah[mt], bb[g][2], bb[g][3]);
                }
        }

        if (kt < 15) store_split(pf, smem + SMEM_HDR + (cur ^ 1) * BUFB, rb, k4);
        __syncthreads();
    }

    // ---- epilogue: registers -> gmem -------------------------------------
#pragma unroll
    for (int mt = 0; mt < 2; mt++) {
        const int r0 = m0 + wm * 32 + mt * 16 + (lane >> 2);
        const int r1 = r0 + 8;
        int bi0 = 0, ni0 = 0, bi1 = 0, ni1 = 0;
        if (MODE == 0) {
            bi0 = r0 / NTOK; ni0 = r0 - bi0 * NTOK;
            bi1 = r1 / NTOK; ni1 = r1 - bi1 * NTOK;
        }
#pragma unroll
        for (int nt = 0; nt < 8; nt++) {
            const int colL = wn * 64 + nt * 8 + (lane & 3) * 2;
            const int o = n0 + colL;
            const float b0 = sBias[colL];
            const float b1 = sBias[colL + 1];
            float v0 = acc[mt][nt][0] + b0;
            float v1 = acc[mt][nt][1] + b1;
            float v2 = acc[mt][nt][2] + b0;
            float v3 = acc[mt][nt][3] + b1;
            if (MODE == 0) {
                const int three = o >> 9;
                const int hh    = (o >> 5) & 15;
                const int dd    = o & 31;
                float* dst = (three == 0) ? g_q : (three == 1) ? g_k : g_v;
                if (three == 0) { v0 *= SCALE; v1 *= SCALE; v2 *= SCALE; v3 *= SCALE; }
                const size_t d0 = (((size_t)bi0 * NHEAD + hh) * NTOK + ni0) * HD + dd;
                const size_t d1 = (((size_t)bi1 * NHEAD + hh) * NTOK + ni1) * HD + dd;
                *(float2*)(dst + d0) = make_float2(v0, v1);
                *(float2*)(dst + d1) = make_float2(v2, v3);
            } else {
                *(float2*)(C + (size_t)r0 * DIM + o) = make_float2(v0, v1);
                *(float2*)(C + (size_t)r1 * DIM + o) = make_float2(v2, v3);
            }
        }
    }
}

// ---------------------------------------------------------------------------
// Attention: one block per (b, h). 256 threads.
// ---------------------------------------------------------------------------
__global__ __launch_bounds__(256) void attn_kernel(
    const float* __restrict__ mask, const float* __restrict__ rpb)
{
    const int bh = blockIdx.x;
    const int b  = bh >> 4;
    const int h  = bh & 15;

    __shared__ float sq[NTOK][HD + 1];
    __shared__ float sk[NTOK][HD + 1];
    __shared__ float sv[NTOK][HD + 1];
    __shared__ float s[NTOK][52];
    __shared__ float sb[169];

    const int tid = threadIdx.x;
    const size_t base = (size_t)bh * NTOK * HD;
    const float* qb = g_q + base;
    const float* kb = g_k + base;
    const float* vb = g_v + base;

    for (int p = tid; p < (NTOK * HD) / 4; p += 256) {
        const int r = p * 4;
        const int i = r >> 5;
        const int c = r & 31;
        float4 t;
        t = *(const float4*)(qb + r);
        sq[i][c] = t.x; sq[i][c + 1] = t.y; sq[i][c + 2] = t.z; sq[i][c + 3] = t.w;
        t = *(const float4*)(kb + r);
        sk[i][c] = t.x; sk[i][c + 1] = t.y; sk[i][c + 2] = t.z; sk[i][c + 3] = t.w;
        t = *(const float4*)(vb + r);
        sv[i][c] = t.x; sv[i][c + 1] = t.y; sv[i][c + 2] = t.z; sv[i][c + 3] = t.w;
    }
    for (int p = tid; p < 169; p += 256) sb[p] = rpb[p * NHEAD + h];
    __syncthreads();

    const float* mk = mask + (size_t)(b & (NWIN - 1)) * NTOK * NTOK;

    for (int p = tid; p < NTOK * NTOK; p += 256) {
        const int i = p / NTOK;
        const int j = p - i * NTOK;
        float a = 0.f;
#pragma unroll
        for (int kk = 0; kk < HD; kk++) a += sq[i][kk] * sk[j][kk];
        const int yi = i / 7, xi = i - yi * 7;
        const int yj = j / 7, xj = j - yj * 7;
        const int ridx = (yi - yj + 6) * 13 + (xi - xj + 6);
        s[i][j] = a + sb[ridx] + mk[p];
    }
    __syncthreads();

    const int warp = tid >> 5;
    const int lane = tid & 31;
    for (int i = warp; i < NTOK; i += 8) {
        float v1 = (lane < NTOK) ? s[i][lane] : -1e30f;
        float v2 = (lane + 32 < NTOK) ? s[i][lane + 32] : -1e30f;
        float mx = fmaxf(v1, v2);
#pragma unroll
        for (int off = 16; off > 0; off >>= 1)
            mx = fmaxf(mx, __shfl_xor_sync(0xffffffffu, mx, off));
        float e1 = (lane < NTOK) ? __expf(v1 - mx) : 0.f;
        float e2 = (lane + 32 < NTOK) ? __expf(v2 - mx) : 0.f;
        float sm = e1 + e2;
#pragma unroll
        for (int off = 16; off > 0; off >>= 1)
            sm += __shfl_xor_sync(0xffffffffu, sm, off);
        const float inv = 1.f / sm;
        if (lane < NTOK) s[i][lane] = e1 * inv;
        if (lane + 32 < NTOK) s[i][lane + 32] = e2 * inv;
    }
    __syncthreads();

    for (int p = tid; p < NTOK * HD; p += 256) {
        const int i  = p >> 5;
        const int dd = p & 31;
        float a = 0.f;
#pragma unroll
        for (int j = 0; j < NTOK; j++) a += s[i][j] * sv[j][dd];
        g_ao[((size_t)b * NTOK + i) * DIM + h * HD + dd] = a;
    }
}

extern "C" void kernel_launch(void* const* d_in, const int* in_sizes, int n_in,
                              void* d_out, int out_size)
{
    const float* x      = (const float*)d_in[0];
    const float* mask   = (const float*)d_in[1];
    const float* qkv_w  = (const float*)d_in[2];
    const float* qkv_b  = (const float*)d_in[3];
    const float* proj_w = (const float*)d_in[4];
    const float* proj_b = (const float*)d_in[5];
    const float* rpb    = (const float*)d_in[6];
    float* out = (float*)d_out;

    cudaFuncSetAttribute(mma_gemm<0>, cudaFuncAttributeMaxDynamicSharedMemorySize, SMEM_TOTAL);
    cudaFuncSetAttribute(mma_gemm<1>, cudaFuncAttributeMaxDynamicSharedMemorySize, SMEM_TOTAL);

    // GEMM1: (100352 x 512) @ (1536 x 512)^T -> q/k/v scatter
    mma_gemm<0><<<dim3(1536 / 128, MROWS / 128), 256, SMEM_TOTAL>>>(x, qkv_w, qkv_b, nullptr);
    // attention: one block per (b, h)
    attn_kernel<<<NBAT * NHEAD, 256>>>(mask, rpb);
    // GEMM2: (100352 x 512) @ (512 x 512)^T -> out
    mma_gemm<1><<<dim3(DIM / 128, MROWS / 128), 256, SMEM_TOTAL>>>(nullptr, proj_w, proj_b, out);
}